// round 8
// baseline (speedup 1.0000x reference)
#include <cuda_runtime.h>
#include <cstdint>

#define FULLMASK 0xffffffffu
#define L2E 1.4426950408889634f
#define MAXB 8192

static __device__ int g_perm[MAXB];

static __device__ __forceinline__ float ex2f_(float x) {
    float r; asm("ex2.approx.f32 %0, %1;" : "=f"(r) : "f"(x)); return r;
}
static __device__ __forceinline__ float rcpf_(float x) {
    float r; asm("rcp.approx.f32 %0, %1;" : "=f"(r) : "f"(x)); return r;
}
// sigmoid(x) = 1 - 1/(1+e^x) (kk=L2E,mm=1) ; tanh(x) = 1 - 2/(1+e^{2x}) (kk=2L2E,mm=2)
static __device__ __forceinline__ float gact(float x, float kk, float mm) {
    return fmaf(-mm, rcpf_(1.0f + ex2f_(kk * x)), 1.0f);
}
static __device__ __forceinline__ float tanh_(float x) {
    return fmaf(-2.0f, rcpf_(1.0f + ex2f_(2.0f * L2E * x)), 1.0f);
}

// ---- packed f32x2 helpers ----
static __device__ __forceinline__ uint64_t pk(float lo, float hi) {
    uint64_t r; asm("mov.b64 %0, {%1,%2};" : "=l"(r) : "f"(lo), "f"(hi)); return r;
}
static __device__ __forceinline__ void upk(uint64_t p, float& lo, float& hi) {
    asm("mov.b64 {%0,%1}, %2;" : "=f"(lo), "=f"(hi) : "l"(p));
}
static __device__ __forceinline__ float plo(uint64_t p) {
    float lo, hi; upk(p, lo, hi); return lo;
}
static __device__ __forceinline__ float phi(uint64_t p) {
    float lo, hi; upk(p, lo, hi); return hi;
}
static __device__ __forceinline__ uint64_t fma2(uint64_t a, uint64_t b, uint64_t c) {
    uint64_t d; asm("fma.rn.f32x2 %0, %1, %2, %3;" : "=l"(d) : "l"(a), "l"(b), "l"(c));
    return d;
}
static __device__ __forceinline__ uint64_t add2(uint64_t a, uint64_t b) {
    uint64_t d; asm("add.rn.f32x2 %0, %1, %2;" : "=l"(d) : "l"(a), "l"(b));
    return d;
}
static __device__ __forceinline__ void load8f(float* d, const float* p) {
    float4 a = *(const float4*)(p);
    float4 b = *(const float4*)(p + 4);
    d[0] = a.x; d[1] = a.y; d[2] = a.z; d[3] = a.w;
    d[4] = b.x; d[5] = b.y; d[6] = b.z; d[7] = b.w;
}

// ---- rank-by-counting: perm[rank] = idx, descending length ----
__global__ void rank_kernel(const int* __restrict__ lengths, int B) {
    __shared__ int sl[4096];
    int tid = threadIdx.x;
    for (int j = tid; j < B; j += blockDim.x) sl[j] = lengths[j];
    __syncthreads();
    int idx = blockIdx.x * blockDim.x + tid;
    if (idx >= B) return;
    int L = sl[idx];
    int rank = 0;
    for (int j = 0; j < B; j++) {
        int lj = sl[j];
        rank += (lj > L) || (lj == L && j < idx);
    }
    g_perm[rank] = idx;
}

__global__ void __launch_bounds__(128)
rnn_ac_kernel(const float* __restrict__ seq, const int* __restrict__ lengths,
              const float* __restrict__ Wih0, const float* __restrict__ Whh0,
              const float* __restrict__ bih0, const float* __restrict__ bhh0,
              const float* __restrict__ Wih1, const float* __restrict__ Whh1,
              const float* __restrict__ bih1, const float* __restrict__ bhh1,
              const float* __restrict__ Wl,  const float* __restrict__ bl,
              const float* __restrict__ Wv,  const float* __restrict__ bv,
              const float* __restrict__ Wa,  const float* __restrict__ ba,
              const float* __restrict__ log_std,
              float* __restrict__ out, int B, int S, int use_perm)
{
    __shared__ uint64_t hbuf[4][2][8];   // per-warp double-buffered (h0,h1) pairs

    const int warp = (blockIdx.x * blockDim.x + threadIdx.x) >> 5;
    const int lane = threadIdx.x & 31;   // gate index g (serves both layers)
    const int wI   = threadIdx.x >> 5;
    if (warp >= B) return;
    const int b = use_perm ? g_perm[warp] : warp;

    // pair weights for the h-recurrent dot: wH[k] = (Whh0[g,k], Whh1[g,k])
    uint64_t wH[8];
    // scalar weights for cross terms: x->layer0 and h0->layer1
    float wi0s[8], wi1s[8];
#pragma unroll
    for (int k = 0; k < 8; k++) {
        wH[k]   = pk(Whh0[lane * 8 + k], Whh1[lane * 8 + k]);
        wi0s[k] = Wih0[lane * 8 + k];
        wi1s[k] = Wih1[lane * 8 + k];
    }
    const float b0s = bih0[lane] + bhh0[lane];
    const float b1s = bih1[lane] + bhh1[lane];
    const uint64_t biasp = pk(b0s, b1s);
    const uint64_t z64   = pk(0.0f, 0.0f);

    // lanes 16-23 carry the tanh ('g') gate
    const bool  isg = ((lane >> 3) == 2);
    const float kk  = isg ? 2.0f * L2E : L2E;
    const float mm  = isg ? 2.0f : 1.0f;

    const int Lg = lengths[b];
    const float* xbase = seq + (size_t)b * (size_t)S * 8;

    uint64_t qH[8];            // (h0_k(t-1), h1_k(t-2)) pairs, from smem broadcast
    float c0 = 0.0f, c1 = 0.0f, h1n = 0.0f;

    float xr[8];
    load8f(xr, xbase);         // x_0

    // ---- peel t=0: layer0 only (h0 = c0 = 0) ----
    {
        float aA = fmaf(wi0s[0], xr[0], b0s);
        float aB = wi0s[1] * xr[1];
#pragma unroll
        for (int k = 2; k < 8; k += 2) {
            aA = fmaf(wi0s[k],     xr[k],     aA);
            aB = fmaf(wi0s[k + 1], xr[k + 1], aB);
        }
        float g0 = gact(aA + aB, kk, mm);
        float G0 = __shfl_down_sync(FULLMASK, g0, 16);
        float o0 = __shfl_down_sync(FULLMASK, g0, 24);
        c0 = g0 * G0;                        // f*c=0, i*g
        float h0n = o0 * tanh_(c0);
        if (lane < 8) hbuf[wI][0][lane] = pk(h0n, 0.0f);
        __syncwarp();
        const ulonglong2* src = (const ulonglong2*)&hbuf[wI][0][0];
#pragma unroll
        for (int k = 0; k < 4; k++) {
            ulonglong2 u = src[k];
            qH[2 * k] = u.x; qH[2 * k + 1] = u.y;
        }
        load8f(xr, xbase + (size_t)min(1, Lg - 1) * 8);   // x_1
    }

    // ---- main loop: iteration t = layer0 step t + layer1 step t-1 ----
    for (int t = 1; t <= Lg; t++) {
        float xn[8];
        load8f(xn, xbase + (size_t)min(t + 1, Lg - 1) * 8);
        asm volatile("prefetch.global.L2 [%0];"
                     :: "l"(xbase + (size_t)min(t + 5, Lg - 1) * 8));

        // pair dot: lo = Whh0.h0, hi = Whh1.h1 (qH straight from LDS, no repack)
        uint64_t A  = fma2(wH[0], qH[0], biasp);
        uint64_t Bq = fma2(wH[1], qH[1], z64);
#pragma unroll
        for (int k = 2; k < 8; k += 2) {
            A  = fma2(wH[k],     qH[k],     A);
            Bq = fma2(wH[k + 1], qH[k + 1], Bq);
        }
        uint64_t acc = add2(A, Bq);

        // scalar dot: Wih0 . x_t  (LDG registers used as-is)
        float axA = wi0s[0] * xr[0];
        float axB = wi0s[1] * xr[1];
#pragma unroll
        for (int k = 2; k < 8; k += 2) {
            axA = fmaf(wi0s[k],     xr[k],     axA);
            axB = fmaf(wi0s[k + 1], xr[k + 1], axB);
        }
        // scalar dot: Wih1 . h0(t-1)  (even halves of qH, free half-reads)
        float ahA = wi1s[0] * plo(qH[0]);
        float ahB = wi1s[1] * plo(qH[1]);
#pragma unroll
        for (int k = 2; k < 8; k += 2) {
            ahA = fmaf(wi1s[k],     plo(qH[k]),     ahA);
            ahB = fmaf(wi1s[k + 1], plo(qH[k + 1]), ahB);
        }

        float a0 = plo(acc) + (axA + axB);
        float a1 = phi(acc) + (ahA + ahB);

        float g0 = gact(a0, kk, mm);
        float g1 = gact(a1, kk, mm);

        float f0 = __shfl_down_sync(FULLMASK, g0, 8);
        float G0 = __shfl_down_sync(FULLMASK, g0, 16);
        float o0 = __shfl_down_sync(FULLMASK, g0, 24);
        float f1 = __shfl_down_sync(FULLMASK, g1, 8);
        float G1 = __shfl_down_sync(FULLMASK, g1, 16);
        float o1 = __shfl_down_sync(FULLMASK, g1, 24);

        c0 = fmaf(f0, c0, g0 * G0);
        c1 = fmaf(f1, c1, g1 * G1);
        float h0n = o0 * tanh_(c0);
        h1n       = o1 * tanh_(c1);

        if (lane < 8) hbuf[wI][t & 1][lane] = pk(h0n, h1n);
        __syncwarp();
        const ulonglong2* src = (const ulonglong2*)&hbuf[wI][t & 1][0];
#pragma unroll
        for (int k = 0; k < 4; k++) {
            ulonglong2 u = src[k];
            qH[2 * k] = u.x; qH[2 * k + 1] = u.y;
        }
#pragma unroll
        for (int k = 0; k < 8; k++) xr[k] = xn[k];
    }

    // h1n = layer1 step Lg-1, valid on lanes 0-7
    float h1a[8];
#pragma unroll
    for (int k = 0; k < 8; k++) h1a[k] = __shfl_sync(FULLMASK, h1n, k);

    // ---- heads ----
    float feat[4];
#pragma unroll
    for (int j = 0; j < 4; j++) {
        float a = bl[j];
#pragma unroll
        for (int k = 0; k < 8; k++) a = fmaf(Wl[j * 8 + k], h1a[k], a);
        feat[j] = tanh_(a);
    }

    if (lane == 0) {
        float v = bv[0];
#pragma unroll
        for (int j = 0; j < 4; j++) v = fmaf(Wv[j], feat[j], v);
        out[b] = v;                                   // value [B,1]
    }
    if (lane < 4) {
        float m = ba[lane];
#pragma unroll
        for (int j = 0; j < 4; j++) m = fmaf(Wa[lane * 4 + j], feat[j], m);
        out[B + b * 4 + lane] = m;                    // action_mean [B,4]
        float lsv = log_std[lane];
        out[5 * B + b * 4 + lane] = lsv;              // action_log_std [B,4]
        out[9 * B + b * 4 + lane] = ex2f_(lsv * L2E); // action_std [B,4]
    }
}

extern "C" void kernel_launch(void* const* d_in, const int* in_sizes, int n_in,
                              void* d_out, int out_size)
{
    const float* seq     = (const float*)d_in[0];
    const int*   lengths = (const int*)d_in[1];
    const float* Wih0 = (const float*)d_in[2];
    const float* Whh0 = (const float*)d_in[3];
    const float* bih0 = (const float*)d_in[4];
    const float* bhh0 = (const float*)d_in[5];
    const float* Wih1 = (const float*)d_in[6];
    const float* Whh1 = (const float*)d_in[7];
    const float* bih1 = (const float*)d_in[8];
    const float* bhh1 = (const float*)d_in[9];
    const float* Wl = (const float*)d_in[10];
    const float* bl = (const float*)d_in[11];
    const float* Wv = (const float*)d_in[12];
    const float* bv = (const float*)d_in[13];
    const float* Wa = (const float*)d_in[14];
    const float* ba = (const float*)d_in[15];
    const float* ls = (const float*)d_in[16];
    float* out = (float*)d_out;

    int B = in_sizes[1];
    int S = in_sizes[0] / (B * 8);

    int use_perm = (B <= 4096) ? 1 : 0;
    if (use_perm) {
        int rthreads = 256;
        rank_kernel<<<(B + rthreads - 1) / rthreads, rthreads>>>(lengths, B);
    }

    int threads = 128;                       // 4 warps/CTA, 1 sequence per warp
    int grid = (B * 32 + threads - 1) / threads;
    rnn_ac_kernel<<<grid, threads>>>(seq, lengths, Wih0, Whh0, bih0, bhh0,
                                     Wih1, Whh1, bih1, bhh1,
                                     Wl, bl, Wv, bv, Wa, ba, ls, out, B, S,
                                     use_perm);
}